// round 1
// baseline (speedup 1.0000x reference)
#include <cuda_runtime.h>
#include <cfloat>
#include <math.h>

// Problem-fixed sizes (setup_inputs is deterministic: N=50000, E=800000)
#define NMAX 50000
#define EMAX 800000
#define ETMAX (NMAX + EMAX)

// ---------------- scratch (device globals; no allocation allowed) ----------
__device__ float g_h1[(size_t)NMAX * 128];    // layer1 GEMM output h
__device__ float g_agg1[(size_t)NMAX * 128];  // layer1 aggregated output (init = b1)
__device__ float g_h2[(size_t)NMAX * 128];    // layer2 GEMM output h
__device__ float g_as1[NMAX * 4], g_ad1[NMAX * 4];
__device__ float g_emax1[NMAX * 4], g_den1[NMAX * 4];
__device__ float g_as2[NMAX], g_ad2[NMAX];
__device__ float g_emax2[NMAX], g_den2[NMAX];
__device__ float g_e1[(size_t)ETMAX * 4];     // per-edge e, then ex (in-place)
__device__ float g_e2[(size_t)ETMAX];
__device__ int   g_is64;                      // 1 if edge_index is int64

// ---------------- helpers ---------------------------------------------------
__device__ __forceinline__ float lrelu(float v) {
    return v > 0.f ? v : 0.2f * v;
}

// order-preserving float atomic max (handles negatives via uint min)
__device__ __forceinline__ void atomicMaxFloat(float* addr, float value) {
    if (value >= 0.f)
        atomicMax((int*)addr, __float_as_int(value));
    else
        atomicMin((unsigned int*)addr, __float_as_uint(value));
}

__device__ __forceinline__ int load_idx(const void* ei, long long pos, int is64) {
    if (is64) return (int)((const long long*)ei)[pos];
    return ((const int*)ei)[pos];
}

// ---------------- init: biases into accumulators, stats reset ---------------
__global__ void init_kernel(float* __restrict__ out, const float* __restrict__ b1,
                            const float* __restrict__ b2, int n) {
    int i = blockIdx.x * blockDim.x + threadIdx.x;
    int tot = n * 128;
    if (i < tot) {
        int c = i & 127;
        g_agg1[i] = b1[c];
        out[i]    = b2[c];
    }
    if (i < n * 4) { g_emax1[i] = -FLT_MAX; g_den1[i] = 0.f; }
    if (i < n)     { g_emax2[i] = -FLT_MAX; g_den2[i] = 0.f; }
    if (i == 0) g_is64 = 1;
}

// ---------------- detect int32 vs int64 edge_index --------------------------
// If int64 (values < 2^31), every odd 32-bit word of the buffer is 0.
// If int32, odd words are random node ids (~all nonzero). Runs AFTER init.
__global__ void detect_kernel(const unsigned* __restrict__ w, int e) {
    int lim = min(e, 4096);
    int found = 0;
    for (int i = threadIdx.x; i < lim; i += blockDim.x)
        if (w[2 * i + 1] != 0u) found = 1;
    if (found) g_is64 = 0;   // all writers write 0; benign race
}

// ---------------- fused GEMM (+ attention-coefficient epilogue) -------------
// Block: 32 rows x 128 cols, 256 threads, K=128 in 4 k-tiles of 32.
// LAYER==1: X = x (input), out = g_h1, alphas -> g_as1/g_ad1 (H=4,C=32)
// LAYER==2: X = relu(g_agg1), out = g_h2, alphas -> g_as2/g_ad2 (H=1,C=128)
template <int LAYER>
__global__ void __launch_bounds__(256) gemm_kernel(
    const float* __restrict__ Xin, const float* __restrict__ W,
    const float* __restrict__ asv, const float* __restrict__ adv, int n) {
    __shared__ float sX[32][36];    // padded: avoid 4-way conflicts on sX[r][kk]
    __shared__ float sW[32][132];   // padded

    const float* X = (LAYER == 1) ? Xin : g_agg1;
    int t    = threadIdx.x;
    int row0 = blockIdx.x * 32;
    int r  = t >> 3;      // 0..31 row within tile
    int cg = t & 7;       // 0..7 column group (16 cols each)

    float acc[16];
#pragma unroll
    for (int j = 0; j < 16; j++) acc[j] = 0.f;

    for (int kt = 0; kt < 4; kt++) {
        // load X tile 32x32 (float4 per thread)
        {
            int rr = t >> 3, qq = t & 7;
            int grow = row0 + rr;
            float4 v = make_float4(0.f, 0.f, 0.f, 0.f);
            if (grow < n)
                v = *(const float4*)(X + (size_t)grow * 128 + kt * 32 + qq * 4);
            if (LAYER == 2) {
                v.x = fmaxf(v.x, 0.f); v.y = fmaxf(v.y, 0.f);
                v.z = fmaxf(v.z, 0.f); v.w = fmaxf(v.w, 0.f);
            }
            *(float4*)&sX[rr][qq * 4] = v;
        }
        // load W tile 32x128 (4 float4 per thread)
#pragma unroll
        for (int j = 0; j < 4; j++) {
            int lin = t + j * 256;          // float4 index in [0,1024)
            int kr = lin >> 5, cq = lin & 31;
            *(float4*)&sW[kr][cq * 4] =
                *(const float4*)(W + (size_t)(kt * 32 + kr) * 128 + cq * 4);
        }
        __syncthreads();
#pragma unroll
        for (int kk = 0; kk < 32; kk++) {
            float xv = sX[r][kk];
            float4 w0 = *(float4*)&sW[kk][cg * 16 + 0];
            float4 w1 = *(float4*)&sW[kk][cg * 16 + 4];
            float4 w2 = *(float4*)&sW[kk][cg * 16 + 8];
            float4 w3 = *(float4*)&sW[kk][cg * 16 + 12];
            acc[0]  += xv * w0.x; acc[1]  += xv * w0.y; acc[2]  += xv * w0.z; acc[3]  += xv * w0.w;
            acc[4]  += xv * w1.x; acc[5]  += xv * w1.y; acc[6]  += xv * w1.z; acc[7]  += xv * w1.w;
            acc[8]  += xv * w2.x; acc[9]  += xv * w2.y; acc[10] += xv * w2.z; acc[11] += xv * w2.w;
            acc[12] += xv * w3.x; acc[13] += xv * w3.y; acc[14] += xv * w3.z; acc[15] += xv * w3.w;
        }
        __syncthreads();
    }

    int grow = row0 + r;
    float* H = (LAYER == 1) ? g_h1 : g_h2;
    if (grow < n) {
        float* dst = H + (size_t)grow * 128 + cg * 16;
        *(float4*)(dst + 0)  = make_float4(acc[0], acc[1], acc[2], acc[3]);
        *(float4*)(dst + 4)  = make_float4(acc[4], acc[5], acc[6], acc[7]);
        *(float4*)(dst + 8)  = make_float4(acc[8], acc[9], acc[10], acc[11]);
        *(float4*)(dst + 12) = make_float4(acc[12], acc[13], acc[14], acc[15]);
    }

    // attention coefficients (fused epilogue)
    if (LAYER == 1) {
        int head = cg >> 1;                  // cols 16cg.. lie in head cg/2
        int off  = head * 32 + (cg & 1) * 16;
        float ps = 0.f, pd = 0.f;
#pragma unroll
        for (int j = 0; j < 16; j++) {
            ps += acc[j] * asv[off + j];
            pd += acc[j] * adv[off + j];
        }
        ps += __shfl_xor_sync(0xffffffffu, ps, 1);
        pd += __shfl_xor_sync(0xffffffffu, pd, 1);
        if ((cg & 1) == 0 && grow < n) {
            g_as1[grow * 4 + head] = ps;
            g_ad1[grow * 4 + head] = pd;
        }
    } else {
        float ps = 0.f, pd = 0.f;
#pragma unroll
        for (int j = 0; j < 16; j++) {
            ps += acc[j] * asv[cg * 16 + j];
            pd += acc[j] * adv[cg * 16 + j];
        }
#pragma unroll
        for (int o = 1; o < 8; o <<= 1) {
            ps += __shfl_xor_sync(0xffffffffu, ps, o);
            pd += __shfl_xor_sync(0xffffffffu, pd, o);
        }
        if (cg == 0 && grow < n) {
            g_as2[grow] = ps;
            g_ad2[grow] = pd;
        }
    }
}

// ---------------- pass B: e = leaky(as[src]+ad[dst]); segment max -----------
template <int H>
__global__ void edge_max_kernel(const void* __restrict__ ei, int e, int n) {
    int t = blockIdx.x * blockDim.x + threadIdx.x;
    int et = e + n;
    if (t >= et) return;
    int is64 = g_is64;
    int s, d;
    if (t < e) { s = load_idx(ei, t, is64); d = load_idx(ei, (long long)e + t, is64); }
    else       { s = d = t - e; }

    if (H == 4) {
        float4 a = *(const float4*)(g_as1 + s * 4);
        float4 b = *(const float4*)(g_ad1 + d * 4);
        float4 ev;
        ev.x = lrelu(a.x + b.x); ev.y = lrelu(a.y + b.y);
        ev.z = lrelu(a.z + b.z); ev.w = lrelu(a.w + b.w);
        *(float4*)(g_e1 + (size_t)t * 4) = ev;
        atomicMaxFloat(g_emax1 + d * 4 + 0, ev.x);
        atomicMaxFloat(g_emax1 + d * 4 + 1, ev.y);
        atomicMaxFloat(g_emax1 + d * 4 + 2, ev.z);
        atomicMaxFloat(g_emax1 + d * 4 + 3, ev.w);
    } else {
        float ev = lrelu(g_as2[s] + g_ad2[d]);
        g_e2[t] = ev;
        atomicMaxFloat(g_emax2 + d, ev);
    }
}

// ---------------- pass C: ex = exp(e - max); segment sum ---------------------
template <int H>
__global__ void edge_exp_kernel(const void* __restrict__ ei, int e, int n) {
    int t = blockIdx.x * blockDim.x + threadIdx.x;
    int et = e + n;
    if (t >= et) return;
    int is64 = g_is64;
    int d;
    if (t < e) d = load_idx(ei, (long long)e + t, is64);
    else       d = t - e;

    if (H == 4) {
        float4 ev = *(const float4*)(g_e1 + (size_t)t * 4);
        float4 m  = *(const float4*)(g_emax1 + d * 4);
        float4 ex;
        ex.x = expf(ev.x - m.x); ex.y = expf(ev.y - m.y);
        ex.z = expf(ev.z - m.z); ex.w = expf(ev.w - m.w);
        *(float4*)(g_e1 + (size_t)t * 4) = ex;
        atomicAdd(g_den1 + d * 4 + 0, ex.x);
        atomicAdd(g_den1 + d * 4 + 1, ex.y);
        atomicAdd(g_den1 + d * 4 + 2, ex.z);
        atomicAdd(g_den1 + d * 4 + 3, ex.w);
    } else {
        float ex = expf(g_e2[t] - g_emax2[d]);
        g_e2[t] = ex;
        atomicAdd(g_den2 + d, ex);
    }
}

// ---------------- pass D: out[dst] += alpha * h[src] (warp per edge) --------
template <int H>
__global__ void edge_agg_kernel(const void* __restrict__ ei, int e, int n,
                                float* __restrict__ out2) {
    int gtid = blockIdx.x * blockDim.x + threadIdx.x;
    int warp = gtid >> 5;
    int lane = threadIdx.x & 31;
    int et = e + n;
    if (warp >= et) return;
    int is64 = g_is64;
    int s, d;
    if (warp < e) { s = load_idx(ei, warp, is64); d = load_idx(ei, (long long)e + warp, is64); }
    else          { s = d = warp - e; }

    const float* hsrc = (H == 4) ? g_h1 : g_h2;
    float*       out  = (H == 4) ? g_agg1 : out2;

    float alpha;
    if (H == 4) {
        int head = lane >> 3;   // channels lane*4..+3 lie in head lane/8
        alpha = g_e1[(size_t)warp * 4 + head] / fmaxf(g_den1[d * 4 + head], 1e-16f);
    } else {
        alpha = g_e2[warp] / fmaxf(g_den2[d], 1e-16f);
    }

    float4 hv = *(const float4*)(hsrc + (size_t)s * 128 + lane * 4);
    float* dst = out + (size_t)d * 128 + lane * 4;
    atomicAdd(dst + 0, alpha * hv.x);
    atomicAdd(dst + 1, alpha * hv.y);
    atomicAdd(dst + 2, alpha * hv.z);
    atomicAdd(dst + 3, alpha * hv.w);
}

// ---------------- launcher ---------------------------------------------------
extern "C" void kernel_launch(void* const* d_in, const int* in_sizes, int n_in,
                              void* d_out, int out_size) {
    const float* x   = (const float*)d_in[0];
    const void*  ei  = d_in[1];
    const float* W1  = (const float*)d_in[2];
    const float* as1 = (const float*)d_in[3];
    const float* ad1 = (const float*)d_in[4];
    const float* b1  = (const float*)d_in[5];
    const float* W2  = (const float*)d_in[6];
    const float* as2 = (const float*)d_in[7];
    const float* ad2 = (const float*)d_in[8];
    const float* b2  = (const float*)d_in[9];
    float* out = (float*)d_out;

    int n  = in_sizes[0] / 128;
    int e  = in_sizes[1] / 2;
    int et = e + n;

    init_kernel<<<(n * 128 + 255) / 256, 256>>>(out, b1, b2, n);
    detect_kernel<<<1, 256>>>((const unsigned*)ei, e);

    // ---- layer 1 (H=4, C=32)
    gemm_kernel<1><<<(n + 31) / 32, 256>>>(x, W1, as1, ad1, n);
    edge_max_kernel<4><<<(et + 255) / 256, 256>>>(ei, e, n);
    edge_exp_kernel<4><<<(et + 255) / 256, 256>>>(ei, e, n);
    edge_agg_kernel<4><<<(et * 32 + 255) / 256, 256>>>(ei, e, n, out);

    // ---- layer 2 (H=1, C=128); relu+bias fused into GEMM2 load / init
    gemm_kernel<2><<<(n + 31) / 32, 256>>>(x /*unused*/, W2, as2, ad2, n);
    edge_max_kernel<1><<<(et + 255) / 256, 256>>>(ei, e, n);
    edge_exp_kernel<1><<<(et + 255) / 256, 256>>>(ei, e, n);
    edge_agg_kernel<1><<<(et * 32 + 255) / 256, 256>>>(ei, e, n, out);
}

// round 6
// speedup vs baseline: 1.4676x; 1.4676x over previous
#include <cuda_runtime.h>
#include <cfloat>
#include <math.h>

// Problem-fixed sizes (setup_inputs is deterministic: N=50000, E=800000)
#define NMAX 50000
#define EMAX 800000
#define ETMAX (NMAX + EMAX)

// ---------------- scratch (device globals; no allocation allowed) ----------
__device__ float g_h1[(size_t)NMAX * 128];    // layer1 GEMM output h
__device__ float g_agg1[(size_t)NMAX * 128];  // layer1 aggregated output (+b1, pre-relu)
__device__ float g_h2[(size_t)NMAX * 128];    // layer2 GEMM output h
__device__ float g_as1[NMAX * 4], g_ad1[NMAX * 4];
__device__ float g_as2[NMAX], g_ad2[NMAX];
__device__ int   g_cnt[NMAX];                 // in-degree histogram
__device__ int   g_cursor[NMAX];              // scatter cursors
__device__ int   g_rowptr[NMAX + 1];          // CSR row pointers (incoming edges per dst)
__device__ int   g_col[ETMAX];                // CSR: src node id per incoming edge
__device__ int   g_is64;                      // 1 if edge_index is int64

// ---------------- helpers ---------------------------------------------------
__device__ __forceinline__ float lrelu(float v) {
    return v > 0.f ? v : 0.2f * v;
}

__device__ __forceinline__ int load_idx(const void* ei, long long pos, int is64) {
    if (is64) return (int)((const long long*)ei)[pos];
    return ((const int*)ei)[pos];
}

// ---------------- init: zero CSR counters -----------------------------------
__global__ void init_kernel(int n) {
    int i = blockIdx.x * blockDim.x + threadIdx.x;
    if (i < n) { g_cnt[i] = 0; g_cursor[i] = 0; }
    if (i == 0) g_is64 = 1;
}

// ---------------- detect int32 vs int64 edge_index --------------------------
// If int64 (values < 2^31), every odd 32-bit word of the buffer is 0.
__global__ void detect_kernel(const unsigned* __restrict__ w, int e) {
    int lim = min(e, 4096);
    int found = 0;
    for (int i = threadIdx.x; i < lim; i += blockDim.x)
        if (w[2 * i + 1] != 0u) found = 1;
    if (found) g_is64 = 0;   // all writers write 0; benign race
}

// ---------------- CSR build: histogram --------------------------------------
__global__ void deg_kernel(const void* __restrict__ ei, int e, int n) {
    int t = blockIdx.x * blockDim.x + threadIdx.x;
    int et = e + n;
    if (t >= et) return;
    int is64 = g_is64;
    int d = (t < e) ? load_idx(ei, (long long)e + t, is64) : (t - e);
    atomicAdd(&g_cnt[d], 1);
}

// ---------------- CSR build: exclusive scan over g_cnt (single block) -------
__global__ void __launch_bounds__(1024) scan_kernel(int n) {
    __shared__ int sums[1024];
    int t   = threadIdx.x;
    int per = (n + 1023) / 1024;
    int s0  = t * per, s1 = min(s0 + per, n);
    int s = 0;
    for (int i = s0; i < s1; i++) s += g_cnt[i];
    sums[t] = s;
    __syncthreads();
    for (int off = 1; off < 1024; off <<= 1) {
        int v = (t >= off) ? sums[t - off] : 0;
        __syncthreads();
        sums[t] += v;
        __syncthreads();
    }
    int base = (t == 0) ? 0 : sums[t - 1];
    for (int i = s0; i < s1; i++) {
        g_rowptr[i] = base;
        base += g_cnt[i];
    }
    if (t == 1023) g_rowptr[n] = sums[1023];
}

// ---------------- CSR build: scatter src ids --------------------------------
__global__ void scatter_kernel(const void* __restrict__ ei, int e, int n) {
    int t = blockIdx.x * blockDim.x + threadIdx.x;
    int et = e + n;
    if (t >= et) return;
    int is64 = g_is64;
    int s, d;
    if (t < e) { s = load_idx(ei, t, is64); d = load_idx(ei, (long long)e + t, is64); }
    else       { s = d = t - e; }
    int pos = g_rowptr[d] + atomicAdd(&g_cursor[d], 1);
    g_col[pos] = s;
}

// ---------------- fused GEMM (+ attention-coefficient epilogue) -------------
// Block: 32 rows x 128 cols, 256 threads, K=128 in 4 k-tiles of 32.
// LAYER==1: X = x (input), out = g_h1, alphas -> g_as1/g_ad1 (H=4,C=32)
// LAYER==2: X = relu(g_agg1), out = g_h2, alphas -> g_as2/g_ad2 (H=1,C=128)
template <int LAYER>
__global__ void __launch_bounds__(256) gemm_kernel(
    const float* __restrict__ Xin, const float* __restrict__ W,
    const float* __restrict__ asv, const float* __restrict__ adv, int n) {
    __shared__ float sX[32][36];
    __shared__ float sW[32][132];

    const float* X = (LAYER == 1) ? Xin : g_agg1;
    int t    = threadIdx.x;
    int row0 = blockIdx.x * 32;
    int r  = t >> 3;      // 0..31 row within tile
    int cg = t & 7;       // 0..7 column group (16 cols each)

    float acc[16];
#pragma unroll
    for (int j = 0; j < 16; j++) acc[j] = 0.f;

    for (int kt = 0; kt < 4; kt++) {
        {
            int rr = t >> 3, qq = t & 7;
            int grow = row0 + rr;
            float4 v = make_float4(0.f, 0.f, 0.f, 0.f);
            if (grow < n)
                v = *(const float4*)(X + (size_t)grow * 128 + kt * 32 + qq * 4);
            if (LAYER == 2) {
                v.x = fmaxf(v.x, 0.f); v.y = fmaxf(v.y, 0.f);
                v.z = fmaxf(v.z, 0.f); v.w = fmaxf(v.w, 0.f);
            }
            *(float4*)&sX[rr][qq * 4] = v;
        }
#pragma unroll
        for (int j = 0; j < 4; j++) {
            int lin = t + j * 256;
            int kr = lin >> 5, cq = lin & 31;
            *(float4*)&sW[kr][cq * 4] =
                *(const float4*)(W + (size_t)(kt * 32 + kr) * 128 + cq * 4);
        }
        __syncthreads();
#pragma unroll
        for (int kk = 0; kk < 32; kk++) {
            float xv = sX[r][kk];
            float4 w0 = *(float4*)&sW[kk][cg * 16 + 0];
            float4 w1 = *(float4*)&sW[kk][cg * 16 + 4];
            float4 w2 = *(float4*)&sW[kk][cg * 16 + 8];
            float4 w3 = *(float4*)&sW[kk][cg * 16 + 12];
            acc[0]  += xv * w0.x; acc[1]  += xv * w0.y; acc[2]  += xv * w0.z; acc[3]  += xv * w0.w;
            acc[4]  += xv * w1.x; acc[5]  += xv * w1.y; acc[6]  += xv * w1.z; acc[7]  += xv * w1.w;
            acc[8]  += xv * w2.x; acc[9]  += xv * w2.y; acc[10] += xv * w2.z; acc[11] += xv * w2.w;
            acc[12] += xv * w3.x; acc[13] += xv * w3.y; acc[14] += xv * w3.z; acc[15] += xv * w3.w;
        }
        __syncthreads();
    }

    int grow = row0 + r;
    float* H = (LAYER == 1) ? g_h1 : g_h2;
    if (grow < n) {
        float* dst = H + (size_t)grow * 128 + cg * 16;
        *(float4*)(dst + 0)  = make_float4(acc[0], acc[1], acc[2], acc[3]);
        *(float4*)(dst + 4)  = make_float4(acc[4], acc[5], acc[6], acc[7]);
        *(float4*)(dst + 8)  = make_float4(acc[8], acc[9], acc[10], acc[11]);
        *(float4*)(dst + 12) = make_float4(acc[12], acc[13], acc[14], acc[15]);
    }

    if (LAYER == 1) {
        int head = cg >> 1;
        int off  = head * 32 + (cg & 1) * 16;
        float ps = 0.f, pd = 0.f;
#pragma unroll
        for (int j = 0; j < 16; j++) {
            ps += acc[j] * asv[off + j];
            pd += acc[j] * adv[off + j];
        }
        ps += __shfl_xor_sync(0xffffffffu, ps, 1);
        pd += __shfl_xor_sync(0xffffffffu, pd, 1);
        if ((cg & 1) == 0 && grow < n) {
            g_as1[grow * 4 + head] = ps;
            g_ad1[grow * 4 + head] = pd;
        }
    } else {
        float ps = 0.f, pd = 0.f;
#pragma unroll
        for (int j = 0; j < 16; j++) {
            ps += acc[j] * asv[cg * 16 + j];
            pd += acc[j] * adv[cg * 16 + j];
        }
#pragma unroll
        for (int o = 1; o < 8; o <<= 1) {
            ps += __shfl_xor_sync(0xffffffffu, ps, o);
            pd += __shfl_xor_sync(0xffffffffu, pd, o);
        }
        if (cg == 0 && grow < n) {
            g_as2[grow] = ps;
            g_ad2[grow] = pd;
        }
    }
}

// ---------------- fused per-node softmax + aggregation (warp per node) ------
// Online (flash-style) softmax over incoming edges; no atomics, no edge scratch.
// H==4: reads g_h1/g_as1/g_ad1, writes g_agg1 (+bias)     [outbuf arg ignored]
// H==1: reads g_h2/g_as2/g_ad2, writes outbuf (+bias)     [harness d_out]
template <int H>
__global__ void __launch_bounds__(256) node_agg_kernel(
    float* __restrict__ outbuf, const float* __restrict__ bias, int n) {
    int warp = (blockIdx.x * blockDim.x + threadIdx.x) >> 5;
    if (warp >= n) return;
    int lane = threadIdx.x & 31;
    int d    = warp;
    int head = (H == 4) ? (lane >> 3) : 0;

    const float* asv  = (H == 4) ? g_as1 : g_as2;
    const float* hsrc = (H == 4) ? g_h1  : g_h2;
    float*       outp = (H == 4) ? g_agg1 : outbuf;   // device-side symbol select
    float ad_d = (H == 4) ? g_ad1[d * 4 + head] : g_ad2[d];

    int beg = g_rowptr[d], end = g_rowptr[d + 1];

    float  m = -FLT_MAX, ssum = 0.f;
    float4 acc = make_float4(0.f, 0.f, 0.f, 0.f);

    for (int j = beg; j < end; j++) {
        int s = __ldg(&g_col[j]);
        float av = (H == 4) ? __ldg(&asv[s * 4 + head]) : __ldg(&asv[s]);
        float e  = lrelu(av + ad_d);
        float mn = fmaxf(m, e);
        float c  = __expf(m - mn);   // 0 on first iter (m = -inf)
        float f  = __expf(e - mn);
        ssum = ssum * c + f;
        float4 hv = *(const float4*)(hsrc + (size_t)s * 128 + lane * 4);
        acc.x = acc.x * c + f * hv.x;
        acc.y = acc.y * c + f * hv.y;
        acc.z = acc.z * c + f * hv.z;
        acc.w = acc.w * c + f * hv.w;
        m = mn;
    }

    float inv = 1.f / fmaxf(ssum, 1e-16f);
    float4 bv = *(const float4*)(bias + lane * 4);
    float4 res;
    res.x = acc.x * inv + bv.x;
    res.y = acc.y * inv + bv.y;
    res.z = acc.z * inv + bv.z;
    res.w = acc.w * inv + bv.w;
    *(float4*)(outp + (size_t)d * 128 + lane * 4) = res;
}

// ---------------- launcher ---------------------------------------------------
extern "C" void kernel_launch(void* const* d_in, const int* in_sizes, int n_in,
                              void* d_out, int out_size) {
    const float* x   = (const float*)d_in[0];
    const void*  ei  = d_in[1];
    const float* W1  = (const float*)d_in[2];
    const float* as1 = (const float*)d_in[3];
    const float* ad1 = (const float*)d_in[4];
    const float* b1  = (const float*)d_in[5];
    const float* W2  = (const float*)d_in[6];
    const float* as2 = (const float*)d_in[7];
    const float* ad2 = (const float*)d_in[8];
    const float* b2  = (const float*)d_in[9];
    float* out = (float*)d_out;

    int n  = in_sizes[0] / 128;
    int e  = in_sizes[1] / 2;
    int et = e + n;

    // CSR build (graph is identical for both layers)
    init_kernel<<<(n + 255) / 256, 256>>>(n);
    detect_kernel<<<1, 256>>>((const unsigned*)ei, e);
    deg_kernel<<<(et + 255) / 256, 256>>>(ei, e, n);
    scan_kernel<<<1, 1024>>>(n);
    scatter_kernel<<<(et + 255) / 256, 256>>>(ei, e, n);

    // ---- layer 1 (H=4, C=32): out-select happens device-side (g_agg1)
    gemm_kernel<1><<<(n + 31) / 32, 256>>>(x, W1, as1, ad1, n);
    node_agg_kernel<4><<<(n * 32 + 255) / 256, 256>>>(out /*ignored*/, b1, n);

    // ---- layer 2 (H=1, C=128); relu fused into GEMM2 A-tile load
    gemm_kernel<2><<<(n + 31) / 32, 256>>>(x /*unused*/, W2, as2, ad2, n);
    node_agg_kernel<1><<<(n * 32 + 255) / 256, 256>>>(out, b2, n);
}

// round 7
// speedup vs baseline: 5.3709x; 3.6597x over previous
#include <cuda_runtime.h>
#include <cfloat>
#include <math.h>

// Problem-fixed sizes (setup_inputs is deterministic: N=50000, E=800000)
#define NMAX 50000
#define EMAX 800000
#define ETMAX (NMAX + EMAX)

// ---------------- scratch (device globals; no allocation allowed) ----------
__device__ float g_h1[(size_t)NMAX * 128];    // layer1 GEMM output h
__device__ float g_agg1[(size_t)NMAX * 128];  // layer1 aggregated output (+b1, pre-relu)
__device__ float g_h2[(size_t)NMAX * 128];    // layer2 GEMM output h
__device__ float g_as1[NMAX * 4], g_ad1[NMAX * 4];
__device__ float g_as2[NMAX], g_ad2[NMAX];
__device__ int   g_cnt[NMAX];                 // in-degree histogram
__device__ int   g_cursor[NMAX];              // scatter cursors
__device__ int   g_pre[NMAX];                 // block-local exclusive scan
__device__ int   g_bsum[256];                 // per-block sums / offsets
__device__ int   g_rowptr[NMAX + 1];          // CSR row pointers
__device__ int   g_col[ETMAX];                // CSR: src node id per incoming edge
__device__ int   g_is64;                      // 1 if edge_index is int64

// ---------------- helpers ---------------------------------------------------
__device__ __forceinline__ float lrelu(float v) {
    return v > 0.f ? v : 0.2f * v;
}

__device__ __forceinline__ int load_idx(const void* ei, long long pos, int is64) {
    if (is64) return (int)((const long long*)ei)[pos];
    return ((const int*)ei)[pos];
}

// block-wide inclusive scan (256 threads)
__device__ __forceinline__ int block_scan_incl(int v) {
    int lane = threadIdx.x & 31, w = threadIdx.x >> 5;
    #pragma unroll
    for (int o = 1; o < 32; o <<= 1) {
        int t = __shfl_up_sync(0xffffffffu, v, o);
        if (lane >= o) v += t;
    }
    __shared__ int ws[8];
    if (lane == 31) ws[w] = v;
    __syncthreads();
    if (w == 0) {
        int s = (lane < 8) ? ws[lane] : 0;
        #pragma unroll
        for (int o = 1; o < 8; o <<= 1) {
            int t = __shfl_up_sync(0xffffffffu, s, o);
            if (lane >= o) s += t;
        }
        if (lane < 8) ws[lane] = s;
    }
    __syncthreads();
    if (w > 0) v += ws[w - 1];
    return v;
}

// ---------------- init -------------------------------------------------------
__global__ void init_kernel(int n) {
    int i = blockIdx.x * blockDim.x + threadIdx.x;
    if (i < n) { g_cnt[i] = 0; g_cursor[i] = 0; }
    if (i == 0) g_is64 = 1;
}

__global__ void detect_kernel(const unsigned* __restrict__ w, int e) {
    int lim = min(e, 4096);
    int found = 0;
    for (int i = threadIdx.x; i < lim; i += blockDim.x)
        if (w[2 * i + 1] != 0u) found = 1;
    if (found) g_is64 = 0;   // all writers write 0; benign race
}

// ---------------- CSR build --------------------------------------------------
__global__ void deg_kernel(const void* __restrict__ ei, int e, int n) {
    int t = blockIdx.x * blockDim.x + threadIdx.x;
    int et = e + n;
    if (t >= et) return;
    int is64 = g_is64;
    int d = (t < e) ? load_idx(ei, (long long)e + t, is64) : (t - e);
    atomicAdd(&g_cnt[d], 1);
}

// phase A: per-block exclusive scan + block totals
__global__ void __launch_bounds__(256) scanA_kernel(int n) {
    int i = blockIdx.x * 256 + threadIdx.x;
    int v = (i < n) ? g_cnt[i] : 0;
    int incl = block_scan_incl(v);
    if (i < n) g_pre[i] = incl - v;
    if (threadIdx.x == 255) g_bsum[blockIdx.x] = incl;
}

// phase B: scan block totals (nb <= 256), exclusive in place
__global__ void __launch_bounds__(256) scanB_kernel(int nb) {
    int t = threadIdx.x;
    int v = (t < nb) ? g_bsum[t] : 0;
    int incl = block_scan_incl(v);
    if (t < nb) g_bsum[t] = incl - v;   // exclusive
}

// phase C: combine into rowptr
__global__ void scanC_kernel(int n) {
    int i = blockIdx.x * 256 + threadIdx.x;
    if (i >= n) return;
    int val = g_pre[i] + g_bsum[i >> 8];
    g_rowptr[i] = val;
    if (i == n - 1) g_rowptr[n] = val + g_cnt[i];
}

__global__ void scatter_kernel(const void* __restrict__ ei, int e, int n) {
    int t = blockIdx.x * blockDim.x + threadIdx.x;
    int et = e + n;
    if (t >= et) return;
    int is64 = g_is64;
    int s, d;
    if (t < e) { s = load_idx(ei, t, is64); d = load_idx(ei, (long long)e + t, is64); }
    else       { s = d = t - e; }
    int pos = g_rowptr[d] + atomicAdd(&g_cursor[d], 1);
    g_col[pos] = s;
}

// ---------------- register-tiled GEMM (+ attention epilogue) ----------------
// BM=64 rows x BN=128 cols per block, BK=16, 256 threads, thread tile 4x8.
// LAYER==1: X = x, out = g_h1, alphas -> g_as1/g_ad1 (H=4, C=32)
// LAYER==2: X = relu(g_agg1), out = g_h2, alphas -> g_as2/g_ad2 (H=1, C=128)
template <int LAYER>
__global__ void __launch_bounds__(256) gemm_kernel(
    const float* __restrict__ Xin, const float* __restrict__ W,
    const float* __restrict__ asv, const float* __restrict__ adv, int n) {
    __shared__ float sX[16][65];    // k-major X tile: sX[k][row]
    __shared__ float sW[16][132];   // sW[k][col]

    const float* X = (LAYER == 1) ? Xin : g_agg1;
    int t    = threadIdx.x;
    int row0 = blockIdx.x * 64;
    int ty = t >> 4;                // 0..15 -> rows ty*4..+3
    int tx = t & 15;                // 0..15 -> cols tx*8..+7
    int r0 = ty * 4, c0 = tx * 8;

    float acc[4][8];
    #pragma unroll
    for (int i = 0; i < 4; i++)
        #pragma unroll
        for (int j = 0; j < 8; j++) acc[i][j] = 0.f;

    int lrow = t >> 2, lkq = t & 3;          // X loader mapping
    int grow_l = row0 + lrow;

    for (int kt = 0; kt < 8; kt++) {
        // load X tile 64x16 (1 float4/thread), transpose into sX[k][row]
        {
            float4 v = make_float4(0.f, 0.f, 0.f, 0.f);
            if (grow_l < n)
                v = *(const float4*)(X + (size_t)grow_l * 128 + kt * 16 + lkq * 4);
            if (LAYER == 2) {
                v.x = fmaxf(v.x, 0.f); v.y = fmaxf(v.y, 0.f);
                v.z = fmaxf(v.z, 0.f); v.w = fmaxf(v.w, 0.f);
            }
            sX[lkq * 4 + 0][lrow] = v.x;
            sX[lkq * 4 + 1][lrow] = v.y;
            sX[lkq * 4 + 2][lrow] = v.z;
            sX[lkq * 4 + 3][lrow] = v.w;
        }
        // load W tile 16x128 (2 float4/thread)
        #pragma unroll
        for (int j = 0; j < 2; j++) {
            int lin = t + j * 256;             // float4 index in [0,512)
            int kr = lin >> 5, cq = lin & 31;
            *(float4*)&sW[kr][cq * 4] =
                *(const float4*)(W + (size_t)(kt * 16 + kr) * 128 + cq * 4);
        }
        __syncthreads();
        #pragma unroll
        for (int kk = 0; kk < 16; kk++) {
            float a0 = sX[kk][r0 + 0], a1 = sX[kk][r0 + 1];
            float a2 = sX[kk][r0 + 2], a3 = sX[kk][r0 + 3];
            float4 b0 = *(float4*)&sW[kk][c0 + 0];
            float4 b1 = *(float4*)&sW[kk][c0 + 4];
            float bb[8] = {b0.x, b0.y, b0.z, b0.w, b1.x, b1.y, b1.z, b1.w};
            #pragma unroll
            for (int j = 0; j < 8; j++) {
                acc[0][j] += a0 * bb[j];
                acc[1][j] += a1 * bb[j];
                acc[2][j] += a2 * bb[j];
                acc[3][j] += a3 * bb[j];
            }
        }
        __syncthreads();
    }

    float* H = (LAYER == 1) ? g_h1 : g_h2;
    #pragma unroll
    for (int i = 0; i < 4; i++) {
        int grow = row0 + r0 + i;
        if (grow < n) {
            float* dst = H + (size_t)grow * 128 + c0;
            *(float4*)(dst + 0) = make_float4(acc[i][0], acc[i][1], acc[i][2], acc[i][3]);
            *(float4*)(dst + 4) = make_float4(acc[i][4], acc[i][5], acc[i][6], acc[i][7]);
        }
    }

    // attention coefficients
    if (LAYER == 1) {
        int head = tx >> 2;                    // cols c0.. lie in head tx/4
        int off  = head * 32 + (tx & 3) * 8;   // offset within head
        #pragma unroll
        for (int i = 0; i < 4; i++) {
            float ps = 0.f, pd = 0.f;
            #pragma unroll
            for (int j = 0; j < 8; j++) {
                ps += acc[i][j] * asv[off + j];
                pd += acc[i][j] * adv[off + j];
            }
            ps += __shfl_xor_sync(0xffffffffu, ps, 1);
            pd += __shfl_xor_sync(0xffffffffu, pd, 1);
            ps += __shfl_xor_sync(0xffffffffu, ps, 2);
            pd += __shfl_xor_sync(0xffffffffu, pd, 2);
            int grow = row0 + r0 + i;
            if ((tx & 3) == 0 && grow < n) {
                g_as1[grow * 4 + head] = ps;
                g_ad1[grow * 4 + head] = pd;
            }
        }
    } else {
        #pragma unroll
        for (int i = 0; i < 4; i++) {
            float ps = 0.f, pd = 0.f;
            #pragma unroll
            for (int j = 0; j < 8; j++) {
                ps += acc[i][j] * asv[c0 + j];
                pd += acc[i][j] * adv[c0 + j];
            }
            #pragma unroll
            for (int o = 1; o < 16; o <<= 1) {
                ps += __shfl_xor_sync(0xffffffffu, ps, o);
                pd += __shfl_xor_sync(0xffffffffu, pd, o);
            }
            int grow = row0 + r0 + i;
            if (tx == 0 && grow < n) {
                g_as2[grow] = ps;
                g_ad2[grow] = pd;
            }
        }
    }
}

// ---------------- fused per-node softmax + aggregation (warp per node) ------
// Two-pass: lane-parallel max (shuffle reduce), then FMA-only accumulate.
// H==4: reads g_h1/g_as1/g_ad1, writes g_agg1 (+bias)     [outbuf arg ignored]
// H==1: reads g_h2/g_as2/g_ad2, writes outbuf (+bias)     [harness d_out]
template <int H>
__global__ void __launch_bounds__(256) node_agg_kernel(
    float* __restrict__ outbuf, const float* __restrict__ bias, int n) {
    int warp = (blockIdx.x * blockDim.x + threadIdx.x) >> 5;
    if (warp >= n) return;
    int lane = threadIdx.x & 31;
    int d    = warp;
    int head = (H == 4) ? (lane >> 3) : 0;

    const float* asv  = (H == 4) ? g_as1 : g_as2;
    const float* hsrc = (H == 4) ? g_h1  : g_h2;
    float*       outp = (H == 4) ? g_agg1 : outbuf;   // device-side symbol select
    float ad_d = (H == 4) ? g_ad1[d * 4 + head] : g_ad2[d];

    int beg = g_rowptr[d], end = g_rowptr[d + 1];

    // ---- pass 1: per-head max, lane-parallel over edges
    float m = -FLT_MAX;
    if (H == 4) {
        for (int j = beg + (lane & 7); j < end; j += 8) {
            int s = __ldg(&g_col[j]);
            m = fmaxf(m, lrelu(__ldg(&asv[s * 4 + head]) + ad_d));
        }
        m = fmaxf(m, __shfl_xor_sync(0xffffffffu, m, 1));
        m = fmaxf(m, __shfl_xor_sync(0xffffffffu, m, 2));
        m = fmaxf(m, __shfl_xor_sync(0xffffffffu, m, 4));
    } else {
        for (int j = beg + lane; j < end; j += 32) {
            m = fmaxf(m, lrelu(__ldg(&asv[g_col[j]]) + ad_d));
        }
        #pragma unroll
        for (int o = 1; o < 32; o <<= 1)
            m = fmaxf(m, __shfl_xor_sync(0xffffffffu, m, o));
    }

    // ---- pass 2: accumulate with known max (no rescaling chain)
    float  ssum = 0.f;
    float4 acc = make_float4(0.f, 0.f, 0.f, 0.f);
    #pragma unroll 2
    for (int j = beg; j < end; j++) {
        int s = __ldg(&g_col[j]);
        float av = (H == 4) ? __ldg(&asv[s * 4 + head]) : __ldg(&asv[s]);
        float f  = __expf(lrelu(av + ad_d) - m);
        ssum += f;
        float4 hv = *(const float4*)(hsrc + (size_t)s * 128 + lane * 4);
        acc.x += f * hv.x;
        acc.y += f * hv.y;
        acc.z += f * hv.z;
        acc.w += f * hv.w;
    }

    float inv = 1.f / fmaxf(ssum, 1e-16f);
    float4 bv = *(const float4*)(bias + lane * 4);
    float4 res;
    res.x = acc.x * inv + bv.x;
    res.y = acc.y * inv + bv.y;
    res.z = acc.z * inv + bv.z;
    res.w = acc.w * inv + bv.w;
    *(float4*)(outp + (size_t)d * 128 + lane * 4) = res;
}

// ---------------- launcher ---------------------------------------------------
extern "C" void kernel_launch(void* const* d_in, const int* in_sizes, int n_in,
                              void* d_out, int out_size) {
    const float* x   = (const float*)d_in[0];
    const void*  ei  = d_in[1];
    const float* W1  = (const float*)d_in[2];
    const float* as1 = (const float*)d_in[3];
    const float* ad1 = (const float*)d_in[4];
    const float* b1  = (const float*)d_in[5];
    const float* W2  = (const float*)d_in[6];
    const float* as2 = (const float*)d_in[7];
    const float* ad2 = (const float*)d_in[8];
    const float* b2  = (const float*)d_in[9];
    float* out = (float*)d_out;

    int n  = in_sizes[0] / 128;
    int e  = in_sizes[1] / 2;
    int et = e + n;
    int nb = (n + 255) / 256;

    // CSR build (graph is identical for both layers)
    init_kernel<<<(n + 255) / 256, 256>>>(n);
    detect_kernel<<<1, 256>>>((const unsigned*)ei, e);
    deg_kernel<<<(et + 255) / 256, 256>>>(ei, e, n);
    scanA_kernel<<<nb, 256>>>(n);
    scanB_kernel<<<1, 256>>>(nb);
    scanC_kernel<<<nb, 256>>>(n);
    scatter_kernel<<<(et + 255) / 256, 256>>>(ei, e, n);

    // ---- layer 1 (H=4, C=32)
    gemm_kernel<1><<<(n + 63) / 64, 256>>>(x, W1, as1, ad1, n);
    node_agg_kernel<4><<<(n * 32 + 255) / 256, 256>>>(out /*ignored*/, b1, n);

    // ---- layer 2 (H=1, C=128); relu fused into GEMM2 A-tile load
    gemm_kernel<2><<<(n + 63) / 64, 256>>>(x /*unused*/, W2, as2, ad2, n);
    node_agg_kernel<1><<<(n * 32 + 255) / 256, 256>>>(out, b2, n);
}